// round 12
// baseline (speedup 1.0000x reference)
#include <cuda_runtime.h>
#include <cuda_bf16.h>
#include <math.h>
#include <stdint.h>

static constexpr int kCN = 768;
static constexpr int kHN = 256;
static constexpr int kWC = 129;
static constexpr int kModes = kHN * kWC;      // 33024
static constexpr float kFwdScale = 0.00276213586400995f;  // 1/sqrt(256*512)
static constexpr float kInvScale = 0.00552427172801990f;  // sqrt(2)/256
static constexpr float kLam = 0.01f;
static constexpr float kTwoPi = 6.283185307179586f;
static constexpr float kC8 = 0.9238795325112867f;   // cos(pi/8)
static constexpr float kS8 = 0.3826834323650898f;   // sin(pi/8)
static constexpr float kR2 = 0.7071067811865476f;   // sqrt(2)/2

static constexpr int kFFTWarps = 26;                 // 832 threads
static constexpr int kFFTThreads = kFFTWarps * 32;

// spectrum scratch, bf16x2 in uint32, layout [ch][y][perm(h)]  (~101 MB)
__device__ uint32_t g_specU[(size_t)kCN * kModes];
__device__ __nv_bfloat16 g_wexp[8][2][192][192];

__device__ __forceinline__ float2 cadd(float2 a, float2 b) { return make_float2(a.x + b.x, a.y + b.y); }
__device__ __forceinline__ float2 csub(float2 a, float2 b) { return make_float2(a.x - b.x, a.y - b.y); }
__device__ __forceinline__ float2 cmul(float2 a, float2 b) { return make_float2(a.x * b.x - a.y * b.y, a.x * b.y + a.y * b.x); }

__device__ __forceinline__ uint32_t f2b(float2 v) {
    __nv_bfloat162 h;
    h.x = __float2bfloat16(v.x);
    h.y = __float2bfloat16(v.y);
    return *reinterpret_cast<uint32_t*>(&h);
}
__device__ __forceinline__ float2 b2f(uint32_t u) {
    __nv_bfloat162 h = *reinterpret_cast<__nv_bfloat162*>(&u);
    return make_float2(__bfloat162float(h.x), __bfloat162float(h.y));
}

// ---- weight expansion: complex w -> real 2x2 blocks, transposed [n][k] ----
__global__ void k_prep(const float* __restrict__ w1, const float* __restrict__ w2) {
    const int idx = blockIdx.x * 256 + threadIdx.x;  // (k*96+i)*96+o
    if (idx >= 8 * 96 * 96) return;
    const int kb = idx / 9216;
    const int rr = idx % 9216;
    const int ci = rr / 96;
    const int co = rr % 96;
    for (int L = 0; L < 2; L++) {
        const float* w = (L == 0) ? w1 : w2;
        const float re = w[idx * 2];
        const float im = w[idx * 2 + 1];
        __nv_bfloat16* W = &g_wexp[kb][L][0][0];
        W[(2 * co) * 192 + 2 * ci]         = __float2bfloat16(re);
        W[(2 * co) * 192 + 2 * ci + 1]     = __float2bfloat16(-im);
        W[(2 * co + 1) * 192 + 2 * ci]     = __float2bfloat16(im);
        W[(2 * co + 1) * 192 + 2 * ci + 1] = __float2bfloat16(re);
    }
}

// ===========================================================================
// Warp-level 256-pt FFT, six-step 32(lanes) x 8(regs).
// run():  input natural (slot j, lane l = x[l+32j]) -> output perm
//         (slot k2, lane l = X[k2 + 8*brev5(l)]).
// runT(): transpose graph -- input perm layout -> output natural.
// ===========================================================================
template <int SIGN>
struct WarpFFT {
    float2 w6, ws16, ws8, ws4, ws2;
    int rb;
    __device__ void init(int l) {
        float s, c;
        sincosf((float)SIGN * kTwoPi * (float)l / 256.0f, &s, &c);        w6   = make_float2(c, s);
        sincosf((float)SIGN * kTwoPi * (float)(l & 15) / 32.0f, &s, &c);  ws16 = make_float2(c, s);
        sincosf((float)SIGN * kTwoPi * (float)(l & 7) / 16.0f, &s, &c);   ws8  = make_float2(c, s);
        sincosf((float)SIGN * kTwoPi * (float)(l & 3) / 8.0f, &s, &c);    ws4  = make_float2(c, s);
        sincosf((float)SIGN * kTwoPi * (float)(l & 1) / 4.0f, &s, &c);    ws2  = make_float2(c, s);
        rb = (int)(__brev((unsigned)l) >> 27);
    }
    __device__ __forceinline__ float2 irot(float2 t) const {
        return (SIGN == -1) ? make_float2(t.y, -t.x) : make_float2(-t.y, t.x);
    }
    __device__ __forceinline__ void fft8(float2 v[8]) const {
        float2 t0 = cadd(v[0], v[4]), t1 = csub(v[0], v[4]);
        float2 t2 = cadd(v[2], v[6]), t3 = csub(v[2], v[6]);
        float2 E0 = cadd(t0, t2), E2 = csub(t0, t2);
        float2 rt = irot(t3);
        float2 E1 = cadd(t1, rt), E3 = csub(t1, rt);
        float2 u0 = cadd(v[1], v[5]), u1 = csub(v[1], v[5]);
        float2 u2 = cadd(v[3], v[7]), u3 = csub(v[3], v[7]);
        float2 O0 = cadd(u0, u2), O2 = csub(u0, u2);
        float2 ru = irot(u3);
        float2 O1 = cadd(u1, ru), O3 = csub(u1, ru);
        float2 q1 = cmul(O1, make_float2(kR2, (float)SIGN * kR2));
        float2 q2 = irot(O2);
        float2 q3 = cmul(O3, make_float2(-kR2, (float)SIGN * kR2));
        v[0] = cadd(E0, O0); v[4] = csub(E0, O0);
        v[1] = cadd(E1, q1); v[5] = csub(E1, q1);
        v[2] = cadd(E2, q2); v[6] = csub(E2, q2);
        v[3] = cadd(E3, q3); v[7] = csub(E3, q3);
    }
    __device__ __forceinline__ void twid(float2 v[8]) const {
        float2 w = w6;
#pragma unroll
        for (int k2 = 1; k2 < 8; k2++) {
            v[k2] = cmul(v[k2], w);
            w = cmul(w, w6);
        }
    }
    __device__ __forceinline__ void stg(float2& a, int m, float2 wt, int l) const {
        float2 p = make_float2(__shfl_xor_sync(0xffffffffu, a.x, m),
                               __shfl_xor_sync(0xffffffffu, a.y, m));
        if (l & m) a = cmul(csub(p, a), wt);
        else a = cadd(a, p);
    }
    __device__ __forceinline__ void stg1(float2& a, int m, int l) const {
        float2 p = make_float2(__shfl_xor_sync(0xffffffffu, a.x, m),
                               __shfl_xor_sync(0xffffffffu, a.y, m));
        a = (l & m) ? csub(p, a) : cadd(a, p);
    }
    __device__ __forceinline__ void stgT(float2& a, int m, float2 wt, int l) const {
        if (l & m) a = cmul(a, wt);
        float2 p = make_float2(__shfl_xor_sync(0xffffffffu, a.x, m),
                               __shfl_xor_sync(0xffffffffu, a.y, m));
        a = (l & m) ? csub(p, a) : cadd(a, p);
    }
    __device__ void run(float2 v[8], int l) const {
        fft8(v);
        twid(v);
#pragma unroll
        for (int j = 0; j < 8; j++) stg(v[j], 16, ws16, l);
#pragma unroll
        for (int j = 0; j < 8; j++) stg(v[j], 8, ws8, l);
#pragma unroll
        for (int j = 0; j < 8; j++) stg(v[j], 4, ws4, l);
#pragma unroll
        for (int j = 0; j < 8; j++) stg(v[j], 2, ws2, l);
#pragma unroll
        for (int j = 0; j < 8; j++) stg1(v[j], 1, l);
    }
    __device__ void runT(float2 v[8], int l) const {
#pragma unroll
        for (int j = 0; j < 8; j++) stg1(v[j], 1, l);
#pragma unroll
        for (int j = 0; j < 8; j++) stgT(v[j], 2, ws2, l);
#pragma unroll
        for (int j = 0; j < 8; j++) stgT(v[j], 4, ws4, l);
#pragma unroll
        for (int j = 0; j < 8; j++) stgT(v[j], 8, ws8, l);
#pragma unroll
        for (int j = 0; j < 8; j++) stgT(v[j], 16, ws16, l);
        twid(v);
        fft8(v);
    }
};

// smem layout for fused FFT kernels (bytes)
static constexpr int kPlaneOff  = 0;                    // 33024 * 4 = 132096
static constexpr int kScrOff    = 132096;               // 26 warps * 2304
static constexpr int kScrStride = 2304;                 // 288 float2
static constexpr int kSmFFT     = 132096 + kFFTWarps * 2304;   // 192000

__device__ __forceinline__ int swz(int k) { return k + (k >> 3); }

// ---- fused forward: per-channel CTA, 832 threads (26 warps) ----
__global__ void __launch_bounds__(kFFTThreads, 1) k_fwd(const float* __restrict__ x) {
    extern __shared__ char sm[];
    uint32_t* plane = (uint32_t*)(sm + kPlaneOff);
    const int tid = threadIdx.x;
    const int w = tid >> 5;
    const int l = tid & 31;
    const int ch = blockIdx.x;

    WarpFFT<-1> F;
    F.init(l);
    float2* scr = (float2*)(sm + kScrOff + w * kScrStride);
    const float2* xc = (const float2*)x + (size_t)ch * kHN * 256;

    float2 base512;
    {
        float s, c;
        sincosf(-kTwoPi * (float)l / 512.0f, &s, &c);
        base512 = make_float2(c, s);
    }
    const float2 step512 = make_float2(kC8, -kS8);  // e^{-i*pi/8}

    // ---- row phase: 512-pt real FFT per row via 256-pt pack trick ----
    for (int h = w; h < 256; h += kFFTWarps) {
        float2 v[8];
#pragma unroll
        for (int j = 0; j < 8; j++) v[j] = xc[(size_t)h * 256 + l + 32 * j];
        F.run(v, l);
#pragma unroll
        for (int k2 = 0; k2 < 8; k2++) scr[swz(k2 + 8 * F.rb)] = v[k2];
        __syncwarp();
        float2 w5 = base512;
#pragma unroll
        for (int j = 0; j < 4; j++) {
            const int k = l + 32 * j;
            const float2 Zk = scr[swz(k)];
            const int km = (256 - k) & 255;
            const float2 Zr = scr[swz(km)];
            const float2 Zc = make_float2(Zr.x, -Zr.y);
            const float2 ed = cmul(w5, csub(Zk, Zc));
            const float2 su = cadd(Zk, Zc);
            plane[h * 129 + k] = f2b(make_float2(0.5f * (su.x + ed.y), 0.5f * (su.y - ed.x)));
            w5 = cmul(w5, step512);
        }
        if (l == 0) {
            const float2 Zk = scr[swz(128)];
            plane[h * 129 + 128] = f2b(make_float2(Zk.x, -Zk.y));
        }
        __syncwarp();
    }
    __syncthreads();

    // ---- column phase: FFT down each column, store perm layout direct ----
    uint32_t* gs = g_specU + (size_t)ch * kModes;
    for (int y = w; y < 129; y += kFFTWarps) {
        float2 v[8];
#pragma unroll
        for (int j = 0; j < 8; j++) v[j] = b2f(plane[(l + 32 * j) * 129 + y]);
        F.run(v, l);
#pragma unroll
        for (int k2 = 0; k2 < 8; k2++)
            gs[y * 256 + k2 * 32 + l] = f2b(make_float2(v[k2].x * kFwdScale, v[k2].y * kFwdScale));
    }
}

// ---- fused inverse: per-channel CTA ----
__global__ void __launch_bounds__(kFFTThreads, 1) k_inv(const float* __restrict__ x, float* __restrict__ out) {
    extern __shared__ char sm[];
    uint32_t* plane = (uint32_t*)(sm + kPlaneOff);
    const int tid = threadIdx.x;
    const int w = tid >> 5;
    const int l = tid & 31;
    const int ch = blockIdx.x;

    WarpFFT<1> F;
    F.init(l);
    float2* scr = (float2*)(sm + kScrOff + w * kScrStride);
    const uint32_t* gs = g_specU + (size_t)ch * kModes;

    // ---- column phase: transpose-graph inverse, perm gmem -> natural plane ----
    for (int y = w; y < 129; y += kFFTWarps) {
        float2 v[8];
#pragma unroll
        for (int k2 = 0; k2 < 8; k2++) v[k2] = b2f(gs[y * 256 + k2 * 32 + l]);
        F.runT(v, l);
#pragma unroll
        for (int j = 0; j < 8; j++) plane[(l + 32 * j) * 129 + y] = f2b(v[j]);
    }
    __syncthreads();

    // ---- row phase: inverse 512-pt real FFT per row + residual ----
    const float2* xc = (const float2*)x + (size_t)ch * kHN * 256;
    float2* oc = (float2*)out + (size_t)ch * kHN * 256;
    float2 base512;
    {
        float s, c;
        sincosf(kTwoPi * (float)l / 512.0f, &s, &c);
        base512 = make_float2(c, s);
    }
    const float2 step512 = make_float2(kC8, kS8);  // e^{+i*pi/8}
    const float2 w5hi0 = make_float2(-base512.y, base512.x);  // base512 * i

    for (int h = w; h < 256; h += kFFTWarps) {
        float2 v[8];
        {
            float2 w5 = base512;
#pragma unroll
            for (int j = 0; j < 4; j++) {
                const int k = l + 32 * j;
                float2 Xk = b2f(plane[h * 129 + k]);
                if (j == 0 && l == 0) Xk.y = 0.f;   // c2r drops Im of DC
                const float2 Ev = make_float2(0.5f * Xk.x, 0.5f * Xk.y);
                const float2 Ov = cmul(w5, Ev);
                v[j] = make_float2(Ev.x - Ov.y, Ev.y + Ov.x);
                w5 = cmul(w5, step512);
            }
        }
        {
            float2 w5 = w5hi0;
#pragma unroll
            for (int j = 4; j < 8; j++) {
                const int km = 256 - (l + 32 * j);  // 1..128
                const float2 Xm = b2f(plane[h * 129 + km]);
                const float2 Ev = make_float2(0.5f * Xm.x, -0.5f * Xm.y);
                const float2 Dd = make_float2(-Ev.x, -Ev.y);
                const float2 Ov = cmul(w5, Dd);
                v[j] = make_float2(Ev.x - Ov.y, Ev.y + Ov.x);
                w5 = cmul(w5, step512);
            }
        }
        F.run(v, l);
#pragma unroll
        for (int k2 = 0; k2 < 8; k2++) scr[swz(k2 + 8 * F.rb)] = v[k2];
        __syncwarp();
#pragma unroll
        for (int j = 0; j < 8; j++) {
            const int n = l + 32 * j;
            const float2 z = scr[swz(n)];
            const float2 rv = xc[(size_t)h * 256 + n];
            oc[(size_t)h * 256 + n] = make_float2(z.x * kInvScale + rv.x,
                                                  z.y * kInvScale + rv.y);
        }
        __syncwarp();
    }
}

// ---- tensor-core MLP: 512 threads, M-tile 256, O reuses A buffer ----
static constexpr int kRowB = 400;
static constexpr int kSmA = 0;               // 256 rows * 400 (A, then O)
static constexpr int kSmW = 102400;          // 192 rows * 400
static constexpr int kSmB1 = 179200;
static constexpr int kSmB2 = 179968;
static constexpr int kSmMlp = 180736;

__device__ __forceinline__ void ldsm_x4(uint32_t* r, uint32_t addr) {
    asm volatile("ldmatrix.sync.aligned.m8n8.x4.shared.b16 {%0,%1,%2,%3}, [%4];"
                 : "=r"(r[0]), "=r"(r[1]), "=r"(r[2]), "=r"(r[3]) : "r"(addr));
}
__device__ __forceinline__ void mma16816(float* c, const uint32_t* a, const uint32_t* b) {
    asm volatile("mma.sync.aligned.m16n8k16.row.col.f32.bf16.bf16.f32 "
                 "{%0,%1,%2,%3}, {%4,%5,%6,%7}, {%8,%9}, {%0,%1,%2,%3};"
                 : "+f"(c[0]), "+f"(c[1]), "+f"(c[2]), "+f"(c[3])
                 : "r"(a[0]), "r"(a[1]), "r"(a[2]), "r"(a[3]), "r"(b[0]), "r"(b[1]));
}

__device__ __forceinline__ void gemm192(float acc[2][12][4], uint32_t aBase, uint32_t wBase,
                                        uint32_t rowA, uint32_t rowB) {
#pragma unroll 2
    for (int kk = 0; kk < 12; kk++) {
        uint32_t af[2][4];
        uint32_t bfr[6][4];
        ldsm_x4(af[0], aBase + rowA + kk * 32);
        ldsm_x4(af[1], aBase + rowA + 16 * kRowB + kk * 32);
#pragma unroll
        for (int bj = 0; bj < 6; bj++)
            ldsm_x4(bfr[bj], wBase + rowB + bj * 16 * kRowB + kk * 32);
#pragma unroll
        for (int mi = 0; mi < 2; mi++)
#pragma unroll
            for (int nj = 0; nj < 12; nj++)
                mma16816(acc[mi][nj], af[mi], &bfr[nj >> 1][(nj & 1) * 2]);
    }
}

__global__ void __launch_bounds__(512, 1)
k_mlp_tc(const float* __restrict__ b1, const float* __restrict__ b2) {
    extern __shared__ char smc[];
    const int tid = threadIdx.x;
    const int lane = tid & 31;
    const int wid = tid >> 5;
    const int warp_m = wid & 7;
    const int warp_n = wid >> 3;
    const int grp = lane >> 2;
    const int tig = lane & 3;
    const int kb = blockIdx.y;
    const size_t m0 = (size_t)blockIdx.x * 256;

    const uint32_t su = (uint32_t)__cvta_generic_to_shared(smc);
    float* sB1 = (float*)(smc + kSmB1);
    float* sB2 = (float*)(smc + kSmB2);

    for (int idx = tid; idx < 96 * 256; idx += 512) {
        const int ci = idx >> 8;
        const int m = idx & 255;
        const uint32_t v = g_specU[((size_t)(kb * 96 + ci)) * kModes + m0 + m];
        *(uint32_t*)(smc + kSmA + m * kRowB + ci * 4) = v;
    }
    {
        const uint4* gw = (const uint4*)&g_wexp[kb][0][0][0];
        for (int idx = tid; idx < 192 * 24; idx += 512)
            *(uint4*)(smc + kSmW + (idx / 24) * kRowB + (idx % 24) * 16) = gw[idx];
    }
    for (int idx = tid; idx < 384; idx += 512) {
        if (idx < 192) sB1[idx] = b1[kb * 192 + idx];
        else sB2[idx - 192] = b2[kb * 192 + idx - 192];
    }
    __syncthreads();

    const uint32_t rowA = (uint32_t)((warp_m * 32 + (lane & 15)) * kRowB + ((lane >> 4) << 4));
    const uint32_t rowB = (uint32_t)((warp_n * 96 + (lane & 7) + ((lane >> 4) << 3)) * kRowB
                                     + ((lane & 8) ? 16 : 0));

    float acc[2][12][4];

    for (int mi = 0; mi < 2; mi++)
        for (int nj = 0; nj < 12; nj++) {
            const int n0 = warp_n * 96 + nj * 8 + 2 * tig;
            acc[mi][nj][0] = sB1[n0];
            acc[mi][nj][1] = sB1[n0 + 1];
            acc[mi][nj][2] = sB1[n0];
            acc[mi][nj][3] = sB1[n0 + 1];
        }
    gemm192(acc, su + kSmA, su + kSmW, rowA, rowB);
    __syncthreads();   // all warps done reading A before O overwrites it

    for (int mi = 0; mi < 2; mi++)
        for (int nj = 0; nj < 12; nj++) {
            const int ml = warp_m * 32 + mi * 16 + grp;
            const int n0 = warp_n * 96 + nj * 8 + 2 * tig;
            __nv_bfloat162 hv;
            hv.x = __float2bfloat16(fmaxf(acc[mi][nj][0], 0.f));
            hv.y = __float2bfloat16(fmaxf(acc[mi][nj][1], 0.f));
            *(__nv_bfloat162*)(smc + kSmA + ml * kRowB + n0 * 2) = hv;
            hv.x = __float2bfloat16(fmaxf(acc[mi][nj][2], 0.f));
            hv.y = __float2bfloat16(fmaxf(acc[mi][nj][3], 0.f));
            *(__nv_bfloat162*)(smc + kSmA + (ml + 8) * kRowB + n0 * 2) = hv;
        }
    {
        const uint4* gw = (const uint4*)&g_wexp[kb][1][0][0];
        for (int idx = tid; idx < 192 * 24; idx += 512)
            *(uint4*)(smc + kSmW + (idx / 24) * kRowB + (idx % 24) * 16) = gw[idx];
    }
    __syncthreads();

    for (int mi = 0; mi < 2; mi++)
        for (int nj = 0; nj < 12; nj++) {
            const int n0 = warp_n * 96 + nj * 8 + 2 * tig;
            acc[mi][nj][0] = sB2[n0];
            acc[mi][nj][1] = sB2[n0 + 1];
            acc[mi][nj][2] = sB2[n0];
            acc[mi][nj][3] = sB2[n0 + 1];
        }
    gemm192(acc, su + kSmA, su + kSmW, rowA, rowB);

    for (int mi = 0; mi < 2; mi++)
        for (int nj = 0; nj < 12; nj++) {
            const int ml = warp_m * 32 + mi * 16 + grp;
            const int n0 = warp_n * 96 + nj * 8 + 2 * tig;
            const int ch = kb * 96 + (n0 >> 1);
            float2 v;
            v.x = copysignf(fmaxf(fabsf(acc[mi][nj][0]) - kLam, 0.f), acc[mi][nj][0]);
            v.y = copysignf(fmaxf(fabsf(acc[mi][nj][1]) - kLam, 0.f), acc[mi][nj][1]);
            g_specU[(size_t)ch * kModes + m0 + ml] = f2b(v);
            v.x = copysignf(fmaxf(fabsf(acc[mi][nj][2]) - kLam, 0.f), acc[mi][nj][2]);
            v.y = copysignf(fmaxf(fabsf(acc[mi][nj][3]) - kLam, 0.f), acc[mi][nj][3]);
            g_specU[(size_t)ch * kModes + m0 + ml + 8] = f2b(v);
        }
}

extern "C" void kernel_launch(void* const* d_in, const int* in_sizes, int n_in,
                              void* d_out, int out_size) {
    (void)in_sizes; (void)n_in; (void)out_size;
    const float* x  = (const float*)d_in[0];
    const float* w1 = (const float*)d_in[1];
    const float* b1 = (const float*)d_in[2];
    const float* w2 = (const float*)d_in[3];
    const float* b2 = (const float*)d_in[4];
    float* out = (float*)d_out;

    cudaFuncSetAttribute(k_fwd, cudaFuncAttributeMaxDynamicSharedMemorySize, kSmFFT);
    cudaFuncSetAttribute(k_inv, cudaFuncAttributeMaxDynamicSharedMemorySize, kSmFFT);
    cudaFuncSetAttribute(k_mlp_tc, cudaFuncAttributeMaxDynamicSharedMemorySize, kSmMlp);

    k_prep<<<288, 256>>>(w1, w2);
    k_fwd<<<kCN, kFFTThreads, kSmFFT>>>(x);

    dim3 gm(kModes / 256, 8);   // 129 x 8
    k_mlp_tc<<<gm, 512, kSmMlp>>>(b1, b2);

    k_inv<<<kCN, kFFTThreads, kSmFFT>>>(x, out);
}

// round 15
// speedup vs baseline: 1.0288x; 1.0288x over previous
#include <cuda_runtime.h>
#include <cuda_bf16.h>
#include <math.h>
#include <stdint.h>

static constexpr int kCN = 768;
static constexpr int kHN = 256;
static constexpr int kWC = 129;
static constexpr int kModes = kHN * kWC;      // 33024
static constexpr float kFwdScale = 0.00276213586400995f;  // 1/sqrt(256*512)
static constexpr float kInvScale = 0.00552427172801990f;  // sqrt(2)/256
static constexpr float kLam = 0.01f;
static constexpr float kTwoPi = 6.283185307179586f;
static constexpr float kC8 = 0.9238795325112867f;   // cos(pi/8)
static constexpr float kS8 = 0.3826834323650898f;   // sin(pi/8)
static constexpr float kR2 = 0.7071067811865476f;   // sqrt(2)/2

static constexpr int kFFTWarps = 24;                 // 768 threads (known-good)
static constexpr int kFFTThreads = kFFTWarps * 32;

// spectrum scratch, bf16x2 in uint32, layout [ch][y][perm(h)]  (~101 MB)
__device__ uint32_t g_specU[(size_t)kCN * kModes];
__device__ __nv_bfloat16 g_wexp[8][2][192][192];

__device__ __forceinline__ float2 cadd(float2 a, float2 b) { return make_float2(a.x + b.x, a.y + b.y); }
__device__ __forceinline__ float2 csub(float2 a, float2 b) { return make_float2(a.x - b.x, a.y - b.y); }
__device__ __forceinline__ float2 cmul(float2 a, float2 b) { return make_float2(a.x * b.x - a.y * b.y, a.x * b.y + a.y * b.x); }

// single-instruction pack: low half = v.x, high half = v.y (rn rounding)
__device__ __forceinline__ uint32_t f2b(float2 v) {
    uint32_t r;
    asm("cvt.rn.bf16x2.f32 %0, %1, %2;" : "=r"(r) : "f"(v.y), "f"(v.x));
    return r;
}
// bf16 -> fp32 is exact via shift (2 ALU ops, no cvt pipe)
__device__ __forceinline__ float2 b2f(uint32_t u) {
    return make_float2(__uint_as_float(u << 16), __uint_as_float(u & 0xffff0000u));
}

// ---- weight expansion: complex w -> real 2x2 blocks, transposed [n][k] ----
__global__ void k_prep(const float* __restrict__ w1, const float* __restrict__ w2) {
    const int idx = blockIdx.x * 256 + threadIdx.x;  // (k*96+i)*96+o
    if (idx >= 8 * 96 * 96) return;
    const int kb = idx / 9216;
    const int rr = idx % 9216;
    const int ci = rr / 96;
    const int co = rr % 96;
    for (int L = 0; L < 2; L++) {
        const float* w = (L == 0) ? w1 : w2;
        const float re = w[idx * 2];
        const float im = w[idx * 2 + 1];
        __nv_bfloat16* W = &g_wexp[kb][L][0][0];
        W[(2 * co) * 192 + 2 * ci]         = __float2bfloat16(re);
        W[(2 * co) * 192 + 2 * ci + 1]     = __float2bfloat16(-im);
        W[(2 * co + 1) * 192 + 2 * ci]     = __float2bfloat16(im);
        W[(2 * co + 1) * 192 + 2 * ci + 1] = __float2bfloat16(re);
    }
}

// ===========================================================================
// Warp-level 256-pt FFT, six-step 32(lanes) x 8(regs).
// run():  natural in -> perm out (slot k2, lane l = X[k2 + 8*brev5(l)]).
// runT(): transpose graph -- perm in -> natural out.
// ===========================================================================
template <int SIGN>
struct WarpFFT {
    float2 w6, ws16, ws8, ws4, ws2;
    int rb;
    __device__ void init(int l) {
        float s, c;
        sincosf((float)SIGN * kTwoPi * (float)l / 256.0f, &s, &c);        w6   = make_float2(c, s);
        sincosf((float)SIGN * kTwoPi * (float)(l & 15) / 32.0f, &s, &c);  ws16 = make_float2(c, s);
        sincosf((float)SIGN * kTwoPi * (float)(l & 7) / 16.0f, &s, &c);   ws8  = make_float2(c, s);
        sincosf((float)SIGN * kTwoPi * (float)(l & 3) / 8.0f, &s, &c);    ws4  = make_float2(c, s);
        sincosf((float)SIGN * kTwoPi * (float)(l & 1) / 4.0f, &s, &c);    ws2  = make_float2(c, s);
        rb = (int)(__brev((unsigned)l) >> 27);
    }
    __device__ __forceinline__ float2 irot(float2 t) const {
        return (SIGN == -1) ? make_float2(t.y, -t.x) : make_float2(-t.y, t.x);
    }
    __device__ __forceinline__ void fft8(float2 v[8]) const {
        float2 t0 = cadd(v[0], v[4]), t1 = csub(v[0], v[4]);
        float2 t2 = cadd(v[2], v[6]), t3 = csub(v[2], v[6]);
        float2 E0 = cadd(t0, t2), E2 = csub(t0, t2);
        float2 rt = irot(t3);
        float2 E1 = cadd(t1, rt), E3 = csub(t1, rt);
        float2 u0 = cadd(v[1], v[5]), u1 = csub(v[1], v[5]);
        float2 u2 = cadd(v[3], v[7]), u3 = csub(v[3], v[7]);
        float2 O0 = cadd(u0, u2), O2 = csub(u0, u2);
        float2 ru = irot(u3);
        float2 O1 = cadd(u1, ru), O3 = csub(u1, ru);
        float2 q1 = cmul(O1, make_float2(kR2, (float)SIGN * kR2));
        float2 q2 = irot(O2);
        float2 q3 = cmul(O3, make_float2(-kR2, (float)SIGN * kR2));
        v[0] = cadd(E0, O0); v[4] = csub(E0, O0);
        v[1] = cadd(E1, q1); v[5] = csub(E1, q1);
        v[2] = cadd(E2, q2); v[6] = csub(E2, q2);
        v[3] = cadd(E3, q3); v[7] = csub(E3, q3);
    }
    __device__ __forceinline__ void twid(float2 v[8]) const {
        float2 w = w6;
#pragma unroll
        for (int k2 = 1; k2 < 8; k2++) {
            v[k2] = cmul(v[k2], w);
            w = cmul(w, w6);
        }
    }
    __device__ __forceinline__ void stg(float2& a, int m, float2 wt, int l) const {
        float2 p = make_float2(__shfl_xor_sync(0xffffffffu, a.x, m),
                               __shfl_xor_sync(0xffffffffu, a.y, m));
        if (l & m) a = cmul(csub(p, a), wt);
        else a = cadd(a, p);
    }
    __device__ __forceinline__ void stg1(float2& a, int m, int l) const {
        float2 p = make_float2(__shfl_xor_sync(0xffffffffu, a.x, m),
                               __shfl_xor_sync(0xffffffffu, a.y, m));
        a = (l & m) ? csub(p, a) : cadd(a, p);
    }
    __device__ __forceinline__ void stgT(float2& a, int m, float2 wt, int l) const {
        if (l & m) a = cmul(a, wt);
        float2 p = make_float2(__shfl_xor_sync(0xffffffffu, a.x, m),
                               __shfl_xor_sync(0xffffffffu, a.y, m));
        a = (l & m) ? csub(p, a) : cadd(a, p);
    }
    __device__ void run(float2 v[8], int l) const {
        fft8(v);
        twid(v);
#pragma unroll
        for (int j = 0; j < 8; j++) stg(v[j], 16, ws16, l);
#pragma unroll
        for (int j = 0; j < 8; j++) stg(v[j], 8, ws8, l);
#pragma unroll
        for (int j = 0; j < 8; j++) stg(v[j], 4, ws4, l);
#pragma unroll
        for (int j = 0; j < 8; j++) stg(v[j], 2, ws2, l);
#pragma unroll
        for (int j = 0; j < 8; j++) stg1(v[j], 1, l);
    }
    __device__ void runT(float2 v[8], int l) const {
#pragma unroll
        for (int j = 0; j < 8; j++) stg1(v[j], 1, l);
#pragma unroll
        for (int j = 0; j < 8; j++) stgT(v[j], 2, ws2, l);
#pragma unroll
        for (int j = 0; j < 8; j++) stgT(v[j], 4, ws4, l);
#pragma unroll
        for (int j = 0; j < 8; j++) stgT(v[j], 8, ws8, l);
#pragma unroll
        for (int j = 0; j < 8; j++) stgT(v[j], 16, ws16, l);
        twid(v);
        fft8(v);
    }
};

// smem layout for fused FFT kernels (bytes)
static constexpr int kPlaneOff  = 0;                    // 33024 * 4 = 132096
static constexpr int kScrOff    = 132096;               // 24 warps * 2304
static constexpr int kScrStride = 2304;                 // 288 float2
static constexpr int kSmFFT     = 132096 + kFFTWarps * 2304;   // 187392

__device__ __forceinline__ int swz(int k) { return k + (k >> 3); }

// ---- fused forward: per-channel CTA, 768 threads (24 warps) ----
__global__ void __launch_bounds__(kFFTThreads, 1) k_fwd(const float* __restrict__ x) {
    extern __shared__ char sm[];
    uint32_t* plane = (uint32_t*)(sm + kPlaneOff);
    const int tid = threadIdx.x;
    const int w = tid >> 5;
    const int l = tid & 31;
    const int ch = blockIdx.x;

    WarpFFT<-1> F;
    F.init(l);
    float2* scr = (float2*)(sm + kScrOff + w * kScrStride);
    const float2* xc = (const float2*)x + (size_t)ch * kHN * 256;

    float2 base512;
    {
        float s, c;
        sincosf(-kTwoPi * (float)l / 512.0f, &s, &c);
        base512 = make_float2(c, s);
    }
    const float2 step512 = make_float2(kC8, -kS8);  // e^{-i*pi/8}

    // ---- row phase: 512-pt real FFT per row via 256-pt pack trick ----
    for (int h = w; h < 256; h += kFFTWarps) {
        float2 v[8];
#pragma unroll
        for (int j = 0; j < 8; j++) v[j] = xc[(size_t)h * 256 + l + 32 * j];
        F.run(v, l);
#pragma unroll
        for (int k2 = 0; k2 < 8; k2++) scr[swz(k2 + 8 * F.rb)] = v[k2];
        __syncwarp();
        float2 w5 = base512;
#pragma unroll
        for (int j = 0; j < 4; j++) {
            const int k = l + 32 * j;
            const float2 Zk = scr[swz(k)];
            const int km = (256 - k) & 255;
            const float2 Zr = scr[swz(km)];
            const float2 Zc = make_float2(Zr.x, -Zr.y);
            const float2 ed = cmul(w5, csub(Zk, Zc));
            const float2 su = cadd(Zk, Zc);
            plane[h * 129 + k] = f2b(make_float2(0.5f * (su.x + ed.y), 0.5f * (su.y - ed.x)));
            w5 = cmul(w5, step512);
        }
        if (l == 0) {
            const float2 Zk = scr[swz(128)];
            plane[h * 129 + 128] = f2b(make_float2(Zk.x, -Zk.y));
        }
        __syncwarp();
    }
    __syncthreads();

    // ---- column phase: FFT down each column, store perm layout direct ----
    uint32_t* gs = g_specU + (size_t)ch * kModes;
    for (int y = w; y < 129; y += kFFTWarps) {
        float2 v[8];
#pragma unroll
        for (int j = 0; j < 8; j++) v[j] = b2f(plane[(l + 32 * j) * 129 + y]);
        F.run(v, l);
#pragma unroll
        for (int k2 = 0; k2 < 8; k2++)
            gs[y * 256 + k2 * 32 + l] = f2b(make_float2(v[k2].x * kFwdScale, v[k2].y * kFwdScale));
    }
}

// ---- fused inverse: per-channel CTA ----
__global__ void __launch_bounds__(kFFTThreads, 1) k_inv(const float* __restrict__ x, float* __restrict__ out) {
    extern __shared__ char sm[];
    uint32_t* plane = (uint32_t*)(sm + kPlaneOff);
    const int tid = threadIdx.x;
    const int w = tid >> 5;
    const int l = tid & 31;
    const int ch = blockIdx.x;

    WarpFFT<1> F;
    F.init(l);
    float2* scr = (float2*)(sm + kScrOff + w * kScrStride);
    const uint32_t* gs = g_specU + (size_t)ch * kModes;

    // ---- column phase: transpose-graph inverse, perm gmem -> natural plane ----
    for (int y = w; y < 129; y += kFFTWarps) {
        float2 v[8];
#pragma unroll
        for (int k2 = 0; k2 < 8; k2++) v[k2] = b2f(gs[y * 256 + k2 * 32 + l]);
        F.runT(v, l);
#pragma unroll
        for (int j = 0; j < 8; j++) plane[(l + 32 * j) * 129 + y] = f2b(v[j]);
    }
    __syncthreads();

    // ---- row phase: inverse 512-pt real FFT per row + residual ----
    const float2* xc = (const float2*)x + (size_t)ch * kHN * 256;
    float2* oc = (float2*)out + (size_t)ch * kHN * 256;
    float2 base512;
    {
        float s, c;
        sincosf(kTwoPi * (float)l / 512.0f, &s, &c);
        base512 = make_float2(c, s);
    }
    const float2 step512 = make_float2(kC8, kS8);  // e^{+i*pi/8}
    const float2 w5hi0 = make_float2(-base512.y, base512.x);  // base512 * i

    for (int h = w; h < 256; h += kFFTWarps) {
        float2 v[8];
        {
            float2 w5 = base512;
#pragma unroll
            for (int j = 0; j < 4; j++) {
                const int k = l + 32 * j;
                float2 Xk = b2f(plane[h * 129 + k]);
                if (j == 0 && l == 0) Xk.y = 0.f;   // c2r drops Im of DC
                const float2 Ev = make_float2(0.5f * Xk.x, 0.5f * Xk.y);
                const float2 Ov = cmul(w5, Ev);
                v[j] = make_float2(Ev.x - Ov.y, Ev.y + Ov.x);
                w5 = cmul(w5, step512);
            }
        }
        {
            float2 w5 = w5hi0;
#pragma unroll
            for (int j = 4; j < 8; j++) {
                const int km = 256 - (l + 32 * j);  // 1..128
                const float2 Xm = b2f(plane[h * 129 + km]);
                const float2 Ev = make_float2(0.5f * Xm.x, -0.5f * Xm.y);
                const float2 Dd = make_float2(-Ev.x, -Ev.y);
                const float2 Ov = cmul(w5, Dd);
                v[j] = make_float2(Ev.x - Ov.y, Ev.y + Ov.x);
                w5 = cmul(w5, step512);
            }
        }
        F.run(v, l);
#pragma unroll
        for (int k2 = 0; k2 < 8; k2++) scr[swz(k2 + 8 * F.rb)] = v[k2];
        __syncwarp();
#pragma unroll
        for (int j = 0; j < 8; j++) {
            const int n = l + 32 * j;
            const float2 z = scr[swz(n)];
            const float2 rv = xc[(size_t)h * 256 + n];
            oc[(size_t)h * 256 + n] = make_float2(z.x * kInvScale + rv.x,
                                                  z.y * kInvScale + rv.y);
        }
        __syncwarp();
    }
}

// ---- tensor-core MLP: 512 threads, M-tile 256, O reuses A buffer ----
static constexpr int kRowB = 400;
static constexpr int kSmA = 0;               // 256 rows * 400 (A, then O)
static constexpr int kSmW = 102400;          // 192 rows * 400
static constexpr int kSmB1 = 179200;
static constexpr int kSmB2 = 179968;
static constexpr int kSmMlp = 180736;

__device__ __forceinline__ void ldsm_x4(uint32_t* r, uint32_t addr) {
    asm volatile("ldmatrix.sync.aligned.m8n8.x4.shared.b16 {%0,%1,%2,%3}, [%4];"
                 : "=r"(r[0]), "=r"(r[1]), "=r"(r[2]), "=r"(r[3]) : "r"(addr));
}
__device__ __forceinline__ void mma16816(float* c, const uint32_t* a, const uint32_t* b) {
    asm volatile("mma.sync.aligned.m16n8k16.row.col.f32.bf16.bf16.f32 "
                 "{%0,%1,%2,%3}, {%4,%5,%6,%7}, {%8,%9}, {%0,%1,%2,%3};"
                 : "+f"(c[0]), "+f"(c[1]), "+f"(c[2]), "+f"(c[3])
                 : "r"(a[0]), "r"(a[1]), "r"(a[2]), "r"(a[3]), "r"(b[0]), "r"(b[1]));
}

__device__ __forceinline__ void gemm192(float acc[2][12][4], uint32_t aBase, uint32_t wBase,
                                        uint32_t rowA, uint32_t rowB) {
#pragma unroll 2
    for (int kk = 0; kk < 12; kk++) {
        uint32_t af[2][4];
        uint32_t bfr[6][4];
        ldsm_x4(af[0], aBase + rowA + kk * 32);
        ldsm_x4(af[1], aBase + rowA + 16 * kRowB + kk * 32);
#pragma unroll
        for (int bj = 0; bj < 6; bj++)
            ldsm_x4(bfr[bj], wBase + rowB + bj * 16 * kRowB + kk * 32);
#pragma unroll
        for (int mi = 0; mi < 2; mi++)
#pragma unroll
            for (int nj = 0; nj < 12; nj++)
                mma16816(acc[mi][nj], af[mi], &bfr[nj >> 1][(nj & 1) * 2]);
    }
}

__global__ void __launch_bounds__(512, 1)
k_mlp_tc(const float* __restrict__ b1, const float* __restrict__ b2) {
    extern __shared__ char smc[];
    const int tid = threadIdx.x;
    const int lane = tid & 31;
    const int wid = tid >> 5;
    const int warp_m = wid & 7;
    const int warp_n = wid >> 3;
    const int grp = lane >> 2;
    const int tig = lane & 3;
    const int kb = blockIdx.y;
    const size_t m0 = (size_t)blockIdx.x * 256;

    const uint32_t su = (uint32_t)__cvta_generic_to_shared(smc);
    float* sB1 = (float*)(smc + kSmB1);
    float* sB2 = (float*)(smc + kSmB2);

    for (int idx = tid; idx < 96 * 256; idx += 512) {
        const int ci = idx >> 8;
        const int m = idx & 255;
        const uint32_t v = g_specU[((size_t)(kb * 96 + ci)) * kModes + m0 + m];
        *(uint32_t*)(smc + kSmA + m * kRowB + ci * 4) = v;
    }
    {
        const uint4* gw = (const uint4*)&g_wexp[kb][0][0][0];
        for (int idx = tid; idx < 192 * 24; idx += 512)
            *(uint4*)(smc + kSmW + (idx / 24) * kRowB + (idx % 24) * 16) = gw[idx];
    }
    for (int idx = tid; idx < 384; idx += 512) {
        if (idx < 192) sB1[idx] = b1[kb * 192 + idx];
        else sB2[idx - 192] = b2[kb * 192 + idx - 192];
    }
    __syncthreads();

    const uint32_t rowA = (uint32_t)((warp_m * 32 + (lane & 15)) * kRowB + ((lane >> 4) << 4));
    const uint32_t rowB = (uint32_t)((warp_n * 96 + (lane & 7) + ((lane >> 4) << 3)) * kRowB
                                     + ((lane & 8) ? 16 : 0));

    float acc[2][12][4];

    for (int mi = 0; mi < 2; mi++)
        for (int nj = 0; nj < 12; nj++) {
            const int n0 = warp_n * 96 + nj * 8 + 2 * tig;
            acc[mi][nj][0] = sB1[n0];
            acc[mi][nj][1] = sB1[n0 + 1];
            acc[mi][nj][2] = sB1[n0];
            acc[mi][nj][3] = sB1[n0 + 1];
        }
    gemm192(acc, su + kSmA, su + kSmW, rowA, rowB);
    __syncthreads();   // all warps done reading A before O overwrites it

    for (int mi = 0; mi < 2; mi++)
        for (int nj = 0; nj < 12; nj++) {
            const int ml = warp_m * 32 + mi * 16 + grp;
            const int n0 = warp_n * 96 + nj * 8 + 2 * tig;
            *(uint32_t*)(smc + kSmA + ml * kRowB + n0 * 2) =
                f2b(make_float2(fmaxf(acc[mi][nj][0], 0.f), fmaxf(acc[mi][nj][1], 0.f)));
            *(uint32_t*)(smc + kSmA + (ml + 8) * kRowB + n0 * 2) =
                f2b(make_float2(fmaxf(acc[mi][nj][2], 0.f), fmaxf(acc[mi][nj][3], 0.f)));
        }
    {
        const uint4* gw = (const uint4*)&g_wexp[kb][1][0][0];
        for (int idx = tid; idx < 192 * 24; idx += 512)
            *(uint4*)(smc + kSmW + (idx / 24) * kRowB + (idx % 24) * 16) = gw[idx];
    }
    __syncthreads();

    for (int mi = 0; mi < 2; mi++)
        for (int nj = 0; nj < 12; nj++) {
            const int n0 = warp_n * 96 + nj * 8 + 2 * tig;
            acc[mi][nj][0] = sB2[n0];
            acc[mi][nj][1] = sB2[n0 + 1];
            acc[mi][nj][2] = sB2[n0];
            acc[mi][nj][3] = sB2[n0 + 1];
        }
    gemm192(acc, su + kSmA, su + kSmW, rowA, rowB);

    for (int mi = 0; mi < 2; mi++)
        for (int nj = 0; nj < 12; nj++) {
            const int ml = warp_m * 32 + mi * 16 + grp;
            const int n0 = warp_n * 96 + nj * 8 + 2 * tig;
            const int ch = kb * 96 + (n0 >> 1);
            float2 v;
            v.x = copysignf(fmaxf(fabsf(acc[mi][nj][0]) - kLam, 0.f), acc[mi][nj][0]);
            v.y = copysignf(fmaxf(fabsf(acc[mi][nj][1]) - kLam, 0.f), acc[mi][nj][1]);
            g_specU[(size_t)ch * kModes + m0 + ml] = f2b(v);
            v.x = copysignf(fmaxf(fabsf(acc[mi][nj][2]) - kLam, 0.f), acc[mi][nj][2]);
            v.y = copysignf(fmaxf(fabsf(acc[mi][nj][3]) - kLam, 0.f), acc[mi][nj][3]);
            g_specU[(size_t)ch * kModes + m0 + ml + 8] = f2b(v);
        }
}

extern "C" void kernel_launch(void* const* d_in, const int* in_sizes, int n_in,
                              void* d_out, int out_size) {
    (void)in_sizes; (void)n_in; (void)out_size;
    const float* x  = (const float*)d_in[0];
    const float* w1 = (const float*)d_in[1];
    const float* b1 = (const float*)d_in[2];
    const float* w2 = (const float*)d_in[3];
    const float* b2 = (const float*)d_in[4];
    float* out = (float*)d_out;

    cudaFuncSetAttribute(k_fwd, cudaFuncAttributeMaxDynamicSharedMemorySize, kSmFFT);
    cudaFuncSetAttribute(k_inv, cudaFuncAttributeMaxDynamicSharedMemorySize, kSmFFT);
    cudaFuncSetAttribute(k_mlp_tc, cudaFuncAttributeMaxDynamicSharedMemorySize, kSmMlp);

    k_prep<<<288, 256>>>(w1, w2);
    k_fwd<<<kCN, kFFTThreads, kSmFFT>>>(x);

    dim3 gm(kModes / 256, 8);   // 129 x 8
    k_mlp_tc<<<gm, 512, kSmMlp>>>(b1, b2);

    k_inv<<<kCN, kFFTThreads, kSmFFT>>>(x, out);
}

// round 17
// speedup vs baseline: 1.0549x; 1.0254x over previous
#include <cuda_runtime.h>
#include <cuda_bf16.h>
#include <math.h>
#include <stdint.h>

static constexpr int kCN = 768;
static constexpr int kHN = 256;
static constexpr int kWC = 129;
static constexpr int kModes = kHN * kWC;      // 33024
static constexpr float kFwdScale = 0.00276213586400995f;  // 1/sqrt(256*512)
static constexpr float kInvScale = 0.00552427172801990f;  // sqrt(2)/256
static constexpr float kLam = 0.01f;
static constexpr float kTwoPi = 6.283185307179586f;
static constexpr float kC8 = 0.9238795325112867f;   // cos(pi/8)
static constexpr float kS8 = 0.3826834323650898f;   // sin(pi/8)
static constexpr float kR2 = 0.7071067811865476f;   // sqrt(2)/2

static constexpr int kFFTWarps = 24;                 // 768 threads (known-good)
static constexpr int kFFTThreads = kFFTWarps * 32;
static constexpr int kPrepBlocks = 96;               // 96*768 = 73728 prep threads

// spectrum scratch, bf16x2 in uint32, layout [ch][y][perm(h)]  (~101 MB)
__device__ uint32_t g_specU[(size_t)kCN * kModes];
// expanded bf16 weights: [block][layer][N=192][K=192], B^T layout for ldsm
__device__ __nv_bfloat16 g_wexp[8][2][192][192];

__device__ __forceinline__ float2 cadd(float2 a, float2 b) { return make_float2(a.x + b.x, a.y + b.y); }
__device__ __forceinline__ float2 csub(float2 a, float2 b) { return make_float2(a.x - b.x, a.y - b.y); }
__device__ __forceinline__ float2 cmul(float2 a, float2 b) { return make_float2(a.x * b.x - a.y * b.y, a.x * b.y + a.y * b.x); }

// single-instruction pack: low half = v.x, high half = v.y (rn rounding)
__device__ __forceinline__ uint32_t f2b(float2 v) {
    uint32_t r;
    asm("cvt.rn.bf16x2.f32 %0, %1, %2;" : "=r"(r) : "f"(v.y), "f"(v.x));
    return r;
}
// bf16 -> fp32 exact via shift
__device__ __forceinline__ float2 b2f(uint32_t u) {
    return make_float2(__uint_as_float(u << 16), __uint_as_float(u & 0xffff0000u));
}

// ===========================================================================
// Warp-level 256-pt FFT, six-step 32(lanes) x 8(regs).  (known-good)
// ===========================================================================
template <int SIGN>
struct WarpFFT {
    float2 w6, ws16, ws8, ws4, ws2;
    int rb;
    __device__ void init(int l) {
        float s, c;
        sincosf((float)SIGN * kTwoPi * (float)l / 256.0f, &s, &c);        w6   = make_float2(c, s);
        sincosf((float)SIGN * kTwoPi * (float)(l & 15) / 32.0f, &s, &c);  ws16 = make_float2(c, s);
        sincosf((float)SIGN * kTwoPi * (float)(l & 7) / 16.0f, &s, &c);   ws8  = make_float2(c, s);
        sincosf((float)SIGN * kTwoPi * (float)(l & 3) / 8.0f, &s, &c);    ws4  = make_float2(c, s);
        sincosf((float)SIGN * kTwoPi * (float)(l & 1) / 4.0f, &s, &c);    ws2  = make_float2(c, s);
        rb = (int)(__brev((unsigned)l) >> 27);
    }
    __device__ __forceinline__ float2 irot(float2 t) const {
        return (SIGN == -1) ? make_float2(t.y, -t.x) : make_float2(-t.y, t.x);
    }
    __device__ __forceinline__ void fft8(float2 v[8]) const {
        float2 t0 = cadd(v[0], v[4]), t1 = csub(v[0], v[4]);
        float2 t2 = cadd(v[2], v[6]), t3 = csub(v[2], v[6]);
        float2 E0 = cadd(t0, t2), E2 = csub(t0, t2);
        float2 rt = irot(t3);
        float2 E1 = cadd(t1, rt), E3 = csub(t1, rt);
        float2 u0 = cadd(v[1], v[5]), u1 = csub(v[1], v[5]);
        float2 u2 = cadd(v[3], v[7]), u3 = csub(v[3], v[7]);
        float2 O0 = cadd(u0, u2), O2 = csub(u0, u2);
        float2 ru = irot(u3);
        float2 O1 = cadd(u1, ru), O3 = csub(u1, ru);
        float2 q1 = cmul(O1, make_float2(kR2, (float)SIGN * kR2));
        float2 q2 = irot(O2);
        float2 q3 = cmul(O3, make_float2(-kR2, (float)SIGN * kR2));
        v[0] = cadd(E0, O0); v[4] = csub(E0, O0);
        v[1] = cadd(E1, q1); v[5] = csub(E1, q1);
        v[2] = cadd(E2, q2); v[6] = csub(E2, q2);
        v[3] = cadd(E3, q3); v[7] = csub(E3, q3);
    }
    __device__ __forceinline__ void twid(float2 v[8]) const {
        float2 w = w6;
#pragma unroll
        for (int k2 = 1; k2 < 8; k2++) {
            v[k2] = cmul(v[k2], w);
            w = cmul(w, w6);
        }
    }
    __device__ __forceinline__ void stg(float2& a, int m, float2 wt, int l) const {
        float2 p = make_float2(__shfl_xor_sync(0xffffffffu, a.x, m),
                               __shfl_xor_sync(0xffffffffu, a.y, m));
        if (l & m) a = cmul(csub(p, a), wt);
        else a = cadd(a, p);
    }
    __device__ __forceinline__ void stg1(float2& a, int m, int l) const {
        float2 p = make_float2(__shfl_xor_sync(0xffffffffu, a.x, m),
                               __shfl_xor_sync(0xffffffffu, a.y, m));
        a = (l & m) ? csub(p, a) : cadd(a, p);
    }
    __device__ __forceinline__ void stgT(float2& a, int m, float2 wt, int l) const {
        if (l & m) a = cmul(a, wt);
        float2 p = make_float2(__shfl_xor_sync(0xffffffffu, a.x, m),
                               __shfl_xor_sync(0xffffffffu, a.y, m));
        a = (l & m) ? csub(p, a) : cadd(a, p);
    }
    __device__ void run(float2 v[8], int l) const {
        fft8(v);
        twid(v);
#pragma unroll
        for (int j = 0; j < 8; j++) stg(v[j], 16, ws16, l);
#pragma unroll
        for (int j = 0; j < 8; j++) stg(v[j], 8, ws8, l);
#pragma unroll
        for (int j = 0; j < 8; j++) stg(v[j], 4, ws4, l);
#pragma unroll
        for (int j = 0; j < 8; j++) stg(v[j], 2, ws2, l);
#pragma unroll
        for (int j = 0; j < 8; j++) stg1(v[j], 1, l);
    }
    __device__ void runT(float2 v[8], int l) const {
#pragma unroll
        for (int j = 0; j < 8; j++) stg1(v[j], 1, l);
#pragma unroll
        for (int j = 0; j < 8; j++) stgT(v[j], 2, ws2, l);
#pragma unroll
        for (int j = 0; j < 8; j++) stgT(v[j], 4, ws4, l);
#pragma unroll
        for (int j = 0; j < 8; j++) stgT(v[j], 8, ws8, l);
#pragma unroll
        for (int j = 0; j < 8; j++) stgT(v[j], 16, ws16, l);
        twid(v);
        fft8(v);
    }
};

// smem layout for fused FFT kernels (bytes)
static constexpr int kPlaneOff  = 0;                    // 33024 * 4 = 132096
static constexpr int kScrOff    = 132096;               // 24 warps * 2304
static constexpr int kScrStride = 2304;                 // 288 float2
static constexpr int kSmFFT     = 132096 + kFFTWarps * 2304;   // 187392

__device__ __forceinline__ int swz(int k) { return k + (k >> 3); }

// ---- fused forward (+ weight expansion in trailing blocks) ----
__global__ void __launch_bounds__(kFFTThreads, 1)
k_fwd(const float* __restrict__ x, const float* __restrict__ w1, const float* __restrict__ w2) {
    const int tid = threadIdx.x;

    if (blockIdx.x >= kCN) {
        // ---- weight expansion: complex w -> real 2x2 blocks, [n][k] ----
        const int idx = (blockIdx.x - kCN) * kFFTThreads + tid;  // (kb*96+ci)*96+co
        if (idx < 8 * 96 * 96) {
            const int kb = idx / 9216;
            const int rr = idx % 9216;
            const int ci = rr / 96;
            const int co = rr % 96;
            for (int L = 0; L < 2; L++) {
                const float* w = (L == 0) ? w1 : w2;
                const float re = w[idx * 2];
                const float im = w[idx * 2 + 1];
                __nv_bfloat16* W = &g_wexp[kb][L][0][0];
                W[(2 * co) * 192 + 2 * ci]         = __float2bfloat16(re);
                W[(2 * co) * 192 + 2 * ci + 1]     = __float2bfloat16(-im);
                W[(2 * co + 1) * 192 + 2 * ci]     = __float2bfloat16(im);
                W[(2 * co + 1) * 192 + 2 * ci + 1] = __float2bfloat16(re);
            }
        }
        return;
    }

    extern __shared__ char sm[];
    uint32_t* plane = (uint32_t*)(sm + kPlaneOff);
    const int w = tid >> 5;
    const int l = tid & 31;
    const int ch = blockIdx.x;

    WarpFFT<-1> F;
    F.init(l);
    float2* scr = (float2*)(sm + kScrOff + w * kScrStride);
    const float2* xc = (const float2*)x + (size_t)ch * kHN * 256;

    float2 base512;
    {
        float s, c;
        sincosf(-kTwoPi * (float)l / 512.0f, &s, &c);
        base512 = make_float2(c, s);
    }
    const float2 step512 = make_float2(kC8, -kS8);  // e^{-i*pi/8}

    // ---- row phase: 512-pt real FFT per row via 256-pt pack trick ----
    for (int h = w; h < 256; h += kFFTWarps) {
        float2 v[8];
#pragma unroll
        for (int j = 0; j < 8; j++) v[j] = xc[(size_t)h * 256 + l + 32 * j];
        F.run(v, l);
#pragma unroll
        for (int k2 = 0; k2 < 8; k2++) scr[swz(k2 + 8 * F.rb)] = v[k2];
        __syncwarp();
        float2 w5 = base512;
#pragma unroll
        for (int j = 0; j < 4; j++) {
            const int k = l + 32 * j;
            const float2 Zk = scr[swz(k)];
            const int km = (256 - k) & 255;
            const float2 Zr = scr[swz(km)];
            const float2 Zc = make_float2(Zr.x, -Zr.y);
            const float2 ed = cmul(w5, csub(Zk, Zc));
            const float2 su = cadd(Zk, Zc);
            plane[h * 129 + k] = f2b(make_float2(0.5f * (su.x + ed.y), 0.5f * (su.y - ed.x)));
            w5 = cmul(w5, step512);
        }
        if (l == 0) {
            const float2 Zk = scr[swz(128)];
            plane[h * 129 + 128] = f2b(make_float2(Zk.x, -Zk.y));
        }
        __syncwarp();
    }
    __syncthreads();

    // ---- column phase: FFT down each column, store perm layout direct ----
    uint32_t* gs = g_specU + (size_t)ch * kModes;
    for (int y = w; y < 129; y += kFFTWarps) {
        float2 v[8];
#pragma unroll
        for (int j = 0; j < 8; j++) v[j] = b2f(plane[(l + 32 * j) * 129 + y]);
        F.run(v, l);
#pragma unroll
        for (int k2 = 0; k2 < 8; k2++)
            gs[y * 256 + k2 * 32 + l] = f2b(make_float2(v[k2].x * kFwdScale, v[k2].y * kFwdScale));
    }
}

// ---- fused inverse: per-channel CTA ----
__global__ void __launch_bounds__(kFFTThreads, 1) k_inv(const float* __restrict__ x, float* __restrict__ out) {
    extern __shared__ char sm[];
    uint32_t* plane = (uint32_t*)(sm + kPlaneOff);
    const int tid = threadIdx.x;
    const int w = tid >> 5;
    const int l = tid & 31;
    const int ch = blockIdx.x;

    WarpFFT<1> F;
    F.init(l);
    float2* scr = (float2*)(sm + kScrOff + w * kScrStride);
    const uint32_t* gs = g_specU + (size_t)ch * kModes;

    // ---- column phase: transpose-graph inverse, perm gmem -> natural plane ----
    for (int y = w; y < 129; y += kFFTWarps) {
        float2 v[8];
#pragma unroll
        for (int k2 = 0; k2 < 8; k2++) v[k2] = b2f(gs[y * 256 + k2 * 32 + l]);
        F.runT(v, l);
#pragma unroll
        for (int j = 0; j < 8; j++) plane[(l + 32 * j) * 129 + y] = f2b(v[j]);
    }
    __syncthreads();

    // ---- row phase: inverse 512-pt real FFT per row + residual ----
    const float2* xc = (const float2*)x + (size_t)ch * kHN * 256;
    float2* oc = (float2*)out + (size_t)ch * kHN * 256;
    float2 base512;
    {
        float s, c;
        sincosf(kTwoPi * (float)l / 512.0f, &s, &c);
        base512 = make_float2(c, s);
    }
    const float2 step512 = make_float2(kC8, kS8);  // e^{+i*pi/8}
    const float2 w5hi0 = make_float2(-base512.y, base512.x);  // base512 * i

    for (int h = w; h < 256; h += kFFTWarps) {
        float2 v[8];
        {
            float2 w5 = base512;
#pragma unroll
            for (int j = 0; j < 4; j++) {
                const int k = l + 32 * j;
                float2 Xk = b2f(plane[h * 129 + k]);
                if (j == 0 && l == 0) Xk.y = 0.f;   // c2r drops Im of DC
                const float2 Ev = make_float2(0.5f * Xk.x, 0.5f * Xk.y);
                const float2 Ov = cmul(w5, Ev);
                v[j] = make_float2(Ev.x - Ov.y, Ev.y + Ov.x);
                w5 = cmul(w5, step512);
            }
        }
        {
            float2 w5 = w5hi0;
#pragma unroll
            for (int j = 4; j < 8; j++) {
                const int km = 256 - (l + 32 * j);  // 1..128
                const float2 Xm = b2f(plane[h * 129 + km]);
                const float2 Ev = make_float2(0.5f * Xm.x, -0.5f * Xm.y);
                const float2 Dd = make_float2(-Ev.x, -Ev.y);
                const float2 Ov = cmul(w5, Dd);
                v[j] = make_float2(Ev.x - Ov.y, Ev.y + Ov.x);
                w5 = cmul(w5, step512);
            }
        }
        F.run(v, l);
#pragma unroll
        for (int k2 = 0; k2 < 8; k2++) scr[swz(k2 + 8 * F.rb)] = v[k2];
        __syncwarp();
#pragma unroll
        for (int j = 0; j < 8; j++) {
            const int n = l + 32 * j;
            const float2 z = scr[swz(n)];
            const float2 rv = xc[(size_t)h * 256 + n];
            oc[(size_t)h * 256 + n] = make_float2(z.x * kInvScale + rv.x,
                                                  z.y * kInvScale + rv.y);
        }
        __syncwarp();
    }
}

// ---- tensor-core MLP: 512 threads, M-tile 256; layer-1 A direct from gmem ----
static constexpr int kRowB = 400;
static constexpr int kSmO = 0;               // 256 rows * 400 (layer-1 output)
static constexpr int kSmW = 102400;          // 192 rows * 400
static constexpr int kSmB1 = 179200;
static constexpr int kSmB2 = 179968;
static constexpr int kSmMlp = 180736;

__device__ __forceinline__ void ldsm_x4(uint32_t* r, uint32_t addr) {
    asm volatile("ldmatrix.sync.aligned.m8n8.x4.shared.b16 {%0,%1,%2,%3}, [%4];"
                 : "=r"(r[0]), "=r"(r[1]), "=r"(r[2]), "=r"(r[3]) : "r"(addr));
}
__device__ __forceinline__ void mma16816(float* c, const uint32_t* a, const uint32_t* b) {
    asm volatile("mma.sync.aligned.m16n8k16.row.col.f32.bf16.bf16.f32 "
                 "{%0,%1,%2,%3}, {%4,%5,%6,%7}, {%8,%9}, {%0,%1,%2,%3};"
                 : "+f"(c[0]), "+f"(c[1]), "+f"(c[2]), "+f"(c[3])
                 : "r"(a[0]), "r"(a[1]), "r"(a[2]), "r"(a[3]), "r"(b[0]), "r"(b[1]));
}

// layer-2 gemm: A (O) and B (W2) both from smem via ldsm
__device__ __forceinline__ void gemm192(float acc[2][12][4], uint32_t aBase, uint32_t wBase,
                                        uint32_t rowA, uint32_t rowB) {
#pragma unroll 2
    for (int kk = 0; kk < 12; kk++) {
        uint32_t af[2][4];
        uint32_t bfr[6][4];
        ldsm_x4(af[0], aBase + rowA + kk * 32);
        ldsm_x4(af[1], aBase + rowA + 16 * kRowB + kk * 32);
#pragma unroll
        for (int bj = 0; bj < 6; bj++)
            ldsm_x4(bfr[bj], wBase + rowB + bj * 16 * kRowB + kk * 32);
#pragma unroll
        for (int mi = 0; mi < 2; mi++)
#pragma unroll
            for (int nj = 0; nj < 12; nj++)
                mma16816(acc[mi][nj], af[mi], &bfr[nj >> 1][(nj & 1) * 2]);
    }
}

__global__ void __launch_bounds__(512, 1)
k_mlp_tc(const float* __restrict__ b1, const float* __restrict__ b2) {
    extern __shared__ char smc[];
    const int tid = threadIdx.x;
    const int lane = tid & 31;
    const int wid = tid >> 5;
    const int warp_m = wid & 7;
    const int warp_n = wid >> 3;
    const int grp = lane >> 2;
    const int tig = lane & 3;
    const int kb = blockIdx.y;
    const size_t m0 = (size_t)blockIdx.x * 256;

    const uint32_t su = (uint32_t)__cvta_generic_to_shared(smc);
    float* sB1 = (float*)(smc + kSmB1);
    float* sB2 = (float*)(smc + kSmB2);

    // W1 + biases into smem (A comes straight from gmem in layer 1)
    {
        const uint4* gw = (const uint4*)&g_wexp[kb][0][0][0];
        for (int idx = tid; idx < 192 * 24; idx += 512)
            *(uint4*)(smc + kSmW + (idx / 24) * kRowB + (idx % 24) * 16) = gw[idx];
    }
    for (int idx = tid; idx < 384; idx += 512) {
        if (idx < 192) sB1[idx] = b1[kb * 192 + idx];
        else sB2[idx - 192] = b2[kb * 192 + idx - 192];
    }
    __syncthreads();

    const uint32_t rowA = (uint32_t)((warp_m * 32 + (lane & 15)) * kRowB + ((lane >> 4) << 4));
    const uint32_t rowB = (uint32_t)((warp_n * 96 + (lane & 7) + ((lane >> 4) << 3)) * kRowB
                                     + ((lane & 8) ? 16 : 0));

    float acc[2][12][4];

    for (int mi = 0; mi < 2; mi++)
        for (int nj = 0; nj < 12; nj++) {
            const int n0 = warp_n * 96 + nj * 8 + 2 * tig;
            acc[mi][nj][0] = sB1[n0];
            acc[mi][nj][1] = sB1[n0 + 1];
            acc[mi][nj][2] = sB1[n0];
            acc[mi][nj][3] = sB1[n0 + 1];
        }

    // ---- layer 1: A fragments loaded directly from g_specU ----
    {
        const size_t rowbase = m0 + warp_m * 32 + grp;   // + mi*16 (+8)
#pragma unroll 2
        for (int kk = 0; kk < 12; kk++) {
            const size_t ch0 = (size_t)(kb * 96 + kk * 8 + tig) * kModes;
            const size_t ch1 = ch0 + 4 * (size_t)kModes;
            uint32_t af[2][4];
#pragma unroll
            for (int mi = 0; mi < 2; mi++) {
                const size_t r = rowbase + mi * 16;
                af[mi][0] = g_specU[ch0 + r];
                af[mi][1] = g_specU[ch0 + r + 8];
                af[mi][2] = g_specU[ch1 + r];
                af[mi][3] = g_specU[ch1 + r + 8];
            }
            uint32_t bfr[6][4];
#pragma unroll
            for (int bj = 0; bj < 6; bj++)
                ldsm_x4(bfr[bj], su + kSmW + rowB + bj * 16 * kRowB + kk * 32);
#pragma unroll
            for (int mi = 0; mi < 2; mi++)
#pragma unroll
                for (int nj = 0; nj < 12; nj++)
                    mma16816(acc[mi][nj], af[mi], &bfr[nj >> 1][(nj & 1) * 2]);
        }
    }
    __syncthreads();   // all warps done with W1 before W2 overwrites it

    // epilogue 1: relu -> bf16 -> O smem
    for (int mi = 0; mi < 2; mi++)
        for (int nj = 0; nj < 12; nj++) {
            const int ml = warp_m * 32 + mi * 16 + grp;
            const int n0 = warp_n * 96 + nj * 8 + 2 * tig;
            *(uint32_t*)(smc + kSmO + ml * kRowB + n0 * 2) =
                f2b(make_float2(fmaxf(acc[mi][nj][0], 0.f), fmaxf(acc[mi][nj][1], 0.f)));
            *(uint32_t*)(smc + kSmO + (ml + 8) * kRowB + n0 * 2) =
                f2b(make_float2(fmaxf(acc[mi][nj][2], 0.f), fmaxf(acc[mi][nj][3], 0.f)));
        }
    {
        const uint4* gw = (const uint4*)&g_wexp[kb][1][0][0];
        for (int idx = tid; idx < 192 * 24; idx += 512)
            *(uint4*)(smc + kSmW + (idx / 24) * kRowB + (idx % 24) * 16) = gw[idx];
    }
    __syncthreads();

    for (int mi = 0; mi < 2; mi++)
        for (int nj = 0; nj < 12; nj++) {
            const int n0 = warp_n * 96 + nj * 8 + 2 * tig;
            acc[mi][nj][0] = sB2[n0];
            acc[mi][nj][1] = sB2[n0 + 1];
            acc[mi][nj][2] = sB2[n0];
            acc[mi][nj][3] = sB2[n0 + 1];
        }
    gemm192(acc, su + kSmO, su + kSmW, rowA, rowB);

    for (int mi = 0; mi < 2; mi++)
        for (int nj = 0; nj < 12; nj++) {
            const int ml = warp_m * 32 + mi * 16 + grp;
            const int n0 = warp_n * 96 + nj * 8 + 2 * tig;
            const int ch = kb * 96 + (n0 >> 1);
            float2 v;
            v.x = copysignf(fmaxf(fabsf(acc[mi][nj][0]) - kLam, 0.f), acc[mi][nj][0]);
            v.y = copysignf(fmaxf(fabsf(acc[mi][nj][1]) - kLam, 0.f), acc[mi][nj][1]);
            g_specU[(size_t)ch * kModes + m0 + ml] = f2b(v);
            v.x = copysignf(fmaxf(fabsf(acc[mi][nj][2]) - kLam, 0.f), acc[mi][nj][2]);
            v.y = copysignf(fmaxf(fabsf(acc[mi][nj][3]) - kLam, 0.f), acc[mi][nj][3]);
            g_specU[(size_t)ch * kModes + m0 + ml + 8] = f2b(v);
        }
}

extern "C" void kernel_launch(void* const* d_in, const int* in_sizes, int n_in,
                              void* d_out, int out_size) {
    (void)in_sizes; (void)n_in; (void)out_size;
    const float* x  = (const float*)d_in[0];
    const float* w1 = (const float*)d_in[1];
    const float* b1 = (const float*)d_in[2];
    const float* w2 = (const float*)d_in[3];
    const float* b2 = (const float*)d_in[4];
    float* out = (float*)d_out;

    cudaFuncSetAttribute(k_fwd, cudaFuncAttributeMaxDynamicSharedMemorySize, kSmFFT);
    cudaFuncSetAttribute(k_inv, cudaFuncAttributeMaxDynamicSharedMemorySize, kSmFFT);
    cudaFuncSetAttribute(k_mlp_tc, cudaFuncAttributeMaxDynamicSharedMemorySize, kSmMlp);

    k_fwd<<<kCN + kPrepBlocks, kFFTThreads, kSmFFT>>>(x, w1, w2);

    dim3 gm(kModes / 256, 8);   // 129 x 8
    k_mlp_tc<<<gm, 512, kSmMlp>>>(b1, b2);

    k_inv<<<kCN, kFFTThreads, kSmFFT>>>(x, out);
}